// round 9
// baseline (speedup 1.0000x reference)
#include <cuda_runtime.h>
#include <stdint.h>
#include <math.h>

#define HH 96
#define WW 96
#define NPIX 9216
#define NB 32
#define NS 50

// ---------------- scratch ----------------
__device__ float    g_trp[NB * 600];          // negated standardized, pair-packed
__device__ float    g_ms[NB * 10];            // mean[5], std[5]
__device__ float4   g_clip4[NB * NPIX];       // img_p (clipped) per pixel
__device__ uint32_t g_rv[NB * NPIX];          // ((bits>>9)+1) | (bg?1<<24:0)
__device__ uint32_t g_hist[NB * 512];         // [img][cls][256]; zeroed by consumer
__device__ uint32_t g_cmax_u[NB * 3];         // idempotent across replays
__device__ int      g_cntA[NB], g_cntB[NB], g_cntC[NB], g_done;

// ---------------- threefry2x32 ----------------
__device__ __forceinline__ void tf2x32(uint32_t k0, uint32_t k1,
                                       uint32_t c0, uint32_t c1,
                                       uint32_t& o0, uint32_t& o1) {
    uint32_t ks2 = k0 ^ k1 ^ 0x1BD11BDAu;
    uint32_t x0 = c0 + k0, x1 = c1 + k1;
#define TF_RND(r) { x0 += x1; x1 = (x1 << (r)) | (x1 >> (32 - (r))); x1 ^= x0; }
    TF_RND(13) TF_RND(15) TF_RND(26) TF_RND(6)   x0 += k1;  x1 += ks2 + 1u;
    TF_RND(17) TF_RND(29) TF_RND(16) TF_RND(24)  x0 += ks2; x1 += k0 + 2u;
    TF_RND(13) TF_RND(15) TF_RND(26) TF_RND(6)   x0 += k0;  x1 += k1 + 3u;
    TF_RND(17) TF_RND(29) TF_RND(16) TF_RND(24)  x0 += k1;  x1 += ks2 + 4u;
    TF_RND(13) TF_RND(15) TF_RND(26) TF_RND(6)   x0 += ks2; x1 += k0 + 5u;
#undef TF_RND
    o0 = x0; o1 = x1;
}

__device__ __forceinline__ void image_keys(int b, uint32_t& f0, uint32_t& f1,
                                           uint32_t& g0, uint32_t& g1) {
    uint32_t kb0, kb1;
    tf2x32(0u, 42u, 0u, (uint32_t)b, kb0, kb1);
    tf2x32(kb0, kb1, 0u, 0u, f0, f1);
    tf2x32(kb0, kb1, 0u, 1u, g0, g1);
}

__device__ __forceinline__ uint32_t rbits(uint32_t k0, uint32_t k1, int p) {
    uint32_t o0, o1;
    tf2x32(k0, k1, 0u, (uint32_t)p, o0, o1);
    return o0 ^ o1;
}

__device__ __forceinline__ float clip255(float x) {
    return fminf(fmaxf(x / 255.0f, 0.0f), 1.0f);
}

// ---------------- packed f32x2 helpers ----------------
__device__ __forceinline__ uint64_t pk2(float lo, float hi) {
    uint64_t r; asm("mov.b64 %0, {%1, %2};" : "=l"(r) : "f"(lo), "f"(hi)); return r;
}
__device__ __forceinline__ void unpk2(float& lo, float& hi, uint64_t v) {
    asm("mov.b64 {%0, %1}, %2;" : "=f"(lo), "=f"(hi) : "l"(v));
}
__device__ __forceinline__ uint64_t add2(uint64_t a, uint64_t b) {
    uint64_t r; asm("add.rn.f32x2 %0, %1, %2;" : "=l"(r) : "l"(a), "l"(b)); return r;
}
__device__ __forceinline__ uint64_t mul2(uint64_t a, uint64_t b) {
    uint64_t r; asm("mul.rn.f32x2 %0, %1, %2;" : "=l"(r) : "l"(a), "l"(b)); return r;
}
__device__ __forceinline__ uint64_t fma2(uint64_t a, uint64_t b, uint64_t c) {
    uint64_t r; asm("fma.rn.f32x2 %0, %1, %2, %3;" : "=l"(r) : "l"(a), "l"(b), "l"(c)); return r;
}

__device__ __forceinline__ void spin_ge(int* addr, int target) {
    while (atomicAdd(addr, 0) < target) __nanosleep(128);
}

// ============ the whole pipeline: 9 blocks per image, spin-synced ============
__global__ void __launch_bounds__(1024, 2) k_all(const float* __restrict__ img,
                                                 float* __restrict__ out) {
    __shared__ uint32_t hist[512];                 // [cls][256] (phase C)
    __shared__ unsigned long long cand[2][512];
    __shared__ int cnts[2], pivots[2];
    __shared__ uint32_t keys4[4], cmu[3];
    __shared__ float cmx[3];
    __shared__ float fe[500];
    __shared__ int sel[100];
    __shared__ float msh[10];
    __shared__ ulonglong2 stq[150];                // phase D train tiles
    __shared__ float ms[10];

    int blk = blockIdx.x, t = threadIdx.x;
    int b = blk / 9, sub = blk % 9;
    int lane = t & 31, wid = t >> 5;
    int p = sub * 1024 + t;

    // ---------- phase A: clip + store + channel max ----------
    if (t < 3) cmu[t] = 0u;
    if (t == 0) {
        uint32_t f0, f1, g0, g1;
        image_keys(b, f0, f1, g0, g1);
        keys4[0] = f0; keys4[1] = f1; keys4[2] = g0; keys4[3] = g1;
    }
    __syncthreads();

    const float* px = img + ((size_t)b * NPIX + p) * 3;
    float c0 = clip255(px[0]);
    float c1 = clip255(px[1]);
    float c2 = clip255(px[2]);
    g_clip4[(size_t)b * NPIX + p] = make_float4(c0, c1, c2, 0.0f);

    uint32_t r0 = __reduce_max_sync(0xFFFFFFFFu, __float_as_uint(c0));
    uint32_t r1 = __reduce_max_sync(0xFFFFFFFFu, __float_as_uint(c1));
    uint32_t r2 = __reduce_max_sync(0xFFFFFFFFu, __float_as_uint(c2));
    if (lane == 0) {
        atomicMax(&cmu[0], r0); atomicMax(&cmu[1], r1); atomicMax(&cmu[2], r2);
    }
    __syncthreads();
    if (t < 3) atomicMax(&g_cmax_u[b * 3 + t], cmu[t]);   // idempotent
    __threadfence();
    __syncthreads();
    if (t == 0) {
        atomicAdd(&g_cntA[b], 1);
        spin_ge(&g_cntA[b], 9);
    }
    __syncthreads();
    __threadfence();

    // ---------- phase B: validity + 1 threefry/pixel + global hist ----------
    if (t < 3) cmx[t] = __uint_as_float(g_cmax_u[b * 3 + t]);
    __syncthreads();
    {
        float v0 = c0 / cmx[0];
        float v1 = c1 / cmx[1];
        float v2 = c2 / cmx[2];
        bool fg = (v0 > 0.0f && v0 < 0.6f) || (v1 > 0.0f && v1 < 0.6f) || (v2 > 0.0f && v2 < 0.6f);
        uint32_t bits = rbits(fg ? keys4[0] : keys4[2], fg ? keys4[1] : keys4[3], p);
        g_rv[(size_t)b * NPIX + p] = ((bits >> 9) + 1u) | (fg ? 0u : (1u << 24));
        atomicAdd(&g_hist[b * 512 + (fg ? 0 : 256) + (bits >> 24)], 1u);
    }
    __threadfence();
    __syncthreads();

    if (sub == 0) {
        // ---------- phase C (block sub 0 only): pick + rank + train ----------
        if (t == 0) {
            atomicAdd(&g_cntB[b], 1);
            spin_ge(&g_cntB[b], 9);
        }
        __syncthreads();
        __threadfence();

        if (t < 512) { hist[t] = g_hist[b * 512 + t]; g_hist[b * 512 + t] = 0u; }
        if (t == 0) { cnts[0] = 0; cnts[1] = 0; }
        __syncthreads();

        // pivots: warp 0 -> fg, warp 1 -> bg
        if (wid < 2) {
            const uint32_t* sh = hist + wid * 256;
            int csum = 0;
            #pragma unroll
            for (int i = 0; i < 8; i++) csum += (int)sh[lane * 8 + i];
            int suf = csum;
            #pragma unroll
            for (int o = 1; o < 32; o <<= 1) {
                int v = __shfl_down_sync(0xFFFFFFFFu, suf, o);
                if (lane + o < 32) suf += v;
            }
            unsigned ball = __ballot_sync(0xFFFFFFFFu, suf >= NS);
            if (ball) {
                int L = 31 - __clz(ball);
                if (lane == L) {
                    int acc = suf - csum;
                    int pv = 8 * L;
                    for (int bin = 8 * L + 7; bin >= 8 * L; bin--) {
                        acc += (int)sh[bin];
                        if (acc >= NS) { pv = bin; break; }
                    }
                    pivots[wid] = pv;
                }
            } else if (lane == 0) pivots[wid] = -1;
        }
        __syncthreads();

        // collect candidates (both classes) over the whole image
        int pv0 = pivots[0], pv1 = pivots[1];
        #pragma unroll
        for (int q = 0; q < 9; q++) {
            int pp = q * 1024 + t;
            uint32_t rv = g_rv[(size_t)b * NPIX + pp];
            int clsv = (int)(rv >> 24);
            uint32_t v = rv & 0xFFFFFFu;
            int pvo = clsv ? pv1 : pv0;
            bool take = (pvo >= 0) ? ((int)((v - 1u) >> 15) >= pvo) : true;
            if (take) {
                int slot = atomicAdd(&cnts[clsv], 1);
                if (slot < 512)
                    cand[clsv][slot] = ((unsigned long long)v << 14) |
                                       (unsigned long long)(NPIX - 1 - pp);
            }
            int o = 1 - clsv;
            if (((o ? pv1 : pv0) < 0) && pp < 100) {
                int slot = atomicAdd(&cnts[o], 1);
                if (slot < 512)
                    cand[o][slot] = (unsigned long long)(NPIX - 1 - pp);
            }
        }
        __syncthreads();

        // rank: threads 0-511 fg, 512-1023 bg
        {
            int cls = t >> 9, i = t & 511;
            int cnt = cnts[cls] < 512 ? cnts[cls] : 512;
            if (i < cnt) {
                unsigned long long ki = cand[cls][i];
                int rank = 0;
                for (int j = 0; j < cnt; j++) rank += (cand[cls][j] > ki);
                if (rank < NS)
                    sel[cls * NS + rank] = NPIX - 1 - (int)(ki & 0x3FFFull);
            }
        }
        __syncthreads();

        // train features + stats + packed negated output
        if (t < 100) {
            int pp = sel[t];
            int ii = pp / WW, jj = pp % WW;
            float4 c = g_clip4[(size_t)b * NPIX + pp];
            fe[t * 5 + 0] = c.x / 255.0f;
            fe[t * 5 + 1] = c.y / 255.0f;
            fe[t * 5 + 2] = c.z / 255.0f;
            fe[t * 5 + 3] = ((float)ii / 96.0f) * 100.0f;
            fe[t * 5 + 4] = ((float)jj / 96.0f) * 100.0f;
        }
        __syncthreads();
        if (t < 5) {
            float s = 0.0f;
            for (int r = 0; r < 100; r++) s += fe[r * 5 + t];
            float m = s / 100.0f;
            float v = 0.0f;
            for (int r = 0; r < 100; r++) { float d = fe[r * 5 + t] - m; v += d * d; }
            msh[t] = m;
            msh[5 + t] = sqrtf(v / 100.0f);
        }
        __syncthreads();
        if (t < 100) {
            int m = t >> 1, h = t & 1;
            float* dst = g_trp + ((size_t)b * 50 + m) * 12;
            #pragma unroll
            for (int f = 0; f < 5; f++)
                dst[f * 2 + h] = -((fe[t * 5 + f] - msh[f]) / msh[5 + f]);
            dst[5 * 2 + h] = 0.0f;
        }
        if (t < 10) g_ms[b * 10 + t] = msh[t];
        __threadfence();
        __syncthreads();
        if (t == 0) atomicAdd(&g_cntC[b], 1);
        __syncthreads();
    } else {
        if (t == 0) {
            atomicAdd(&g_cntB[b], 1);
            spin_ge(&g_cntC[b], 1);
        }
        __syncthreads();
        __threadfence();
    }

    // ---------- phase D: KNN segmentation + masking ----------
    if (t < 150) ((float4*)stq)[t] = ((const float4*)(g_trp + (size_t)b * 600))[t];
    if (t < 10) ms[t] = g_ms[b * 10 + t];
    __syncthreads();

    int i = p / WW, j = p % WW;
    float ts0 = (c0 / 255.0f - ms[0]) / ms[5];
    float ts1 = (c1 / 255.0f - ms[1]) / ms[6];
    float ts2 = (c2 / 255.0f - ms[2]) / ms[7];
    float ts3 = (((float)i / 96.0f) * 100.0f - ms[3]) / ms[8];
    float ts4 = (((float)j / 96.0f) * 100.0f - ms[4]) / ms[9];

    uint64_t tp0 = pk2(ts0, ts0), tp1 = pk2(ts1, ts1), tp2 = pk2(ts2, ts2);
    uint64_t tp3 = pk2(ts3, ts3), tp4 = pk2(ts4, ts4);

    const float INF = __int_as_float(0x7F800000);
    float a1 = INF, a2 = INF;
    float b1 = INF, b2 = INF, b3 = INF, b4 = INF;

    #pragma unroll 5
    for (int m = 0; m < 25; m++) {                  // fg pairs
        ulonglong2 q0 = stq[3 * m], q1 = stq[3 * m + 1], q2 = stq[3 * m + 2];
        uint64_t d0 = add2(tp0, q0.x), d1 = add2(tp1, q0.y);
        uint64_t d2_ = add2(tp2, q1.x), d3 = add2(tp3, q1.y);
        uint64_t d4 = add2(tp4, q2.x);
        uint64_t s = mul2(d0, d0);
        s = fma2(d1, d1, s); s = fma2(d2_, d2_, s);
        s = fma2(d3, d3, s); s = fma2(d4, d4, s);
        float lo, hi; unpk2(lo, hi, s);
        float u = fmaxf(lo, a1); a2 = fminf(u, a2); a1 = fminf(lo, a1);
        u = fmaxf(hi, a1);       a2 = fminf(u, a2); a1 = fminf(hi, a1);
    }
    #pragma unroll 5
    for (int m = 25; m < 50; m++) {                 // bg pairs
        ulonglong2 q0 = stq[3 * m], q1 = stq[3 * m + 1], q2 = stq[3 * m + 2];
        uint64_t d0 = add2(tp0, q0.x), d1 = add2(tp1, q0.y);
        uint64_t d2_ = add2(tp2, q1.x), d3 = add2(tp3, q1.y);
        uint64_t d4 = add2(tp4, q2.x);
        uint64_t s = mul2(d0, d0);
        s = fma2(d1, d1, s); s = fma2(d2_, d2_, s);
        s = fma2(d3, d3, s); s = fma2(d4, d4, s);
        float lo, hi; unpk2(lo, hi, s);
        float u3 = fmaxf(lo, b3), u2 = fmaxf(lo, b2), u1 = fmaxf(lo, b1);
        b4 = fminf(u3, b4); b3 = fminf(u2, b3); b2 = fminf(u1, b2); b1 = fminf(lo, b1);
        u3 = fmaxf(hi, b3); u2 = fmaxf(hi, b2); u1 = fmaxf(hi, b1);
        b4 = fminf(u3, b4); b3 = fminf(u2, b3); b2 = fminf(u1, b2); b1 = fminf(hi, b1);
    }

    bool seg = (sqrtf(a2) <= sqrtf(b4));
    float* o = out + ((size_t)b * NPIX + p) * 3;
    if (seg) { o[0] = c0; o[1] = c1; o[2] = c2; }
    else     { o[0] = 0.0f; o[1] = 0.0f; o[2] = 0.0f; }

    // ---------- reset barrier state for next graph replay ----------
    __threadfence();
    __syncthreads();
    if (t == 0) {
        int d = atomicAdd(&g_done, 1);
        if (d == 287) {
            for (int im = 0; im < NB; im++) {
                g_cntA[im] = 0; g_cntB[im] = 0; g_cntC[im] = 0;
            }
            __threadfence();
            g_done = 0;
        }
    }
}

// ---------------- launch ----------------
extern "C" void kernel_launch(void* const* d_in, const int* in_sizes, int n_in,
                              void* d_out, int out_size) {
    const float* img = (const float*)d_in[0];
    float* out = (float*)d_out;
    k_all<<<NB * 9, 1024>>>(img, out);
}

// round 10
// speedup vs baseline: 1.4659x; 1.4659x over previous
#include <cuda_runtime.h>
#include <stdint.h>
#include <math.h>

#define HH 96
#define WW 96
#define NPIX 9216
#define NB 32
#define NS 50

// ---------------- scratch ----------------
__device__ float    g_trp[NB * 600];          // negated standardized, pair-packed
__device__ float    g_ms[NB * 10];            // mean[5], std[5]
__device__ float4   g_clip4[NB * NPIX];       // img_p (clipped) per pixel
__device__ uint2    g_bits2[NB * NPIX];       // threefry bits for (fg, bg) keys
__device__ uint32_t g_cmax_u[NB * 3];         // idempotent across replays

// ---------------- threefry2x32 ----------------
__device__ __forceinline__ void tf2x32(uint32_t k0, uint32_t k1,
                                       uint32_t c0, uint32_t c1,
                                       uint32_t& o0, uint32_t& o1) {
    uint32_t ks2 = k0 ^ k1 ^ 0x1BD11BDAu;
    uint32_t x0 = c0 + k0, x1 = c1 + k1;
#define TF_RND(r) { x0 += x1; x1 = (x1 << (r)) | (x1 >> (32 - (r))); x1 ^= x0; }
    TF_RND(13) TF_RND(15) TF_RND(26) TF_RND(6)   x0 += k1;  x1 += ks2 + 1u;
    TF_RND(17) TF_RND(29) TF_RND(16) TF_RND(24)  x0 += ks2; x1 += k0 + 2u;
    TF_RND(13) TF_RND(15) TF_RND(26) TF_RND(6)   x0 += k0;  x1 += k1 + 3u;
    TF_RND(17) TF_RND(29) TF_RND(16) TF_RND(24)  x0 += k1;  x1 += ks2 + 4u;
    TF_RND(13) TF_RND(15) TF_RND(26) TF_RND(6)   x0 += ks2; x1 += k0 + 5u;
#undef TF_RND
    o0 = x0; o1 = x1;
}

__device__ __forceinline__ void image_keys(int b, uint32_t& f0, uint32_t& f1,
                                           uint32_t& g0, uint32_t& g1) {
    uint32_t kb0, kb1;
    tf2x32(0u, 42u, 0u, (uint32_t)b, kb0, kb1);
    tf2x32(kb0, kb1, 0u, 0u, f0, f1);
    tf2x32(kb0, kb1, 0u, 1u, g0, g1);
}

__device__ __forceinline__ uint32_t rbits(uint32_t k0, uint32_t k1, int p) {
    uint32_t o0, o1;
    tf2x32(k0, k1, 0u, (uint32_t)p, o0, o1);
    return o0 ^ o1;
}

__device__ __forceinline__ float clip255(float x) {
    return fminf(fmaxf(x / 255.0f, 0.0f), 1.0f);
}

// ---------------- packed f32x2 helpers ----------------
__device__ __forceinline__ uint64_t pk2(float lo, float hi) {
    uint64_t r; asm("mov.b64 %0, {%1, %2};" : "=l"(r) : "f"(lo), "f"(hi)); return r;
}
__device__ __forceinline__ void unpk2(float& lo, float& hi, uint64_t v) {
    asm("mov.b64 {%0, %1}, %2;" : "=f"(lo), "=f"(hi) : "l"(v));
}
__device__ __forceinline__ uint64_t add2(uint64_t a, uint64_t b) {
    uint64_t r; asm("add.rn.f32x2 %0, %1, %2;" : "=l"(r) : "l"(a), "l"(b)); return r;
}
__device__ __forceinline__ uint64_t mul2(uint64_t a, uint64_t b) {
    uint64_t r; asm("mul.rn.f32x2 %0, %1, %2;" : "=l"(r) : "l"(a), "l"(b)); return r;
}
__device__ __forceinline__ uint64_t fma2(uint64_t a, uint64_t b, uint64_t c) {
    uint64_t r; asm("fma.rn.f32x2 %0, %1, %2, %3;" : "=l"(r) : "l"(a), "l"(b), "l"(c)); return r;
}

// ============ K1 (288 blocks): clip + cmax + dual threefry ============
__global__ void __launch_bounds__(1024) k1(const float* __restrict__ img) {
    __shared__ uint32_t keys4[4];
    __shared__ uint32_t cmu[3];
    int blk = blockIdx.x, t = threadIdx.x, lane = t & 31;
    int b = blk / 9, p = (blk % 9) * 1024 + t;

    if (t == 0) {
        uint32_t f0, f1, g0, g1;
        image_keys(b, f0, f1, g0, g1);
        keys4[0] = f0; keys4[1] = f1; keys4[2] = g0; keys4[3] = g1;
    }
    if (t < 3) cmu[t] = 0u;
    __syncthreads();

    const float* px = img + ((size_t)b * NPIX + p) * 3;
    float c0 = clip255(px[0]);
    float c1 = clip255(px[1]);
    float c2 = clip255(px[2]);
    g_clip4[(size_t)b * NPIX + p] = make_float4(c0, c1, c2, 0.0f);

    uint32_t bf = rbits(keys4[0], keys4[1], p);
    uint32_t bg_ = rbits(keys4[2], keys4[3], p);
    g_bits2[(size_t)b * NPIX + p] = make_uint2(bf, bg_);

    uint32_t r0 = __reduce_max_sync(0xFFFFFFFFu, __float_as_uint(c0));
    uint32_t r1 = __reduce_max_sync(0xFFFFFFFFu, __float_as_uint(c1));
    uint32_t r2 = __reduce_max_sync(0xFFFFFFFFu, __float_as_uint(c2));
    if (lane == 0) {
        atomicMax(&cmu[0], r0); atomicMax(&cmu[1], r1); atomicMax(&cmu[2], r2);
    }
    __syncthreads();
    if (t < 3) atomicMax(&g_cmax_u[b * 3 + t], cmu[t]);   // idempotent across replays
}

// ============ K2 (32 blocks): validity + pick + rank + train ============
__global__ void __launch_bounds__(1024) k2() {
    __shared__ uint32_t hist[512];                 // [cls][256]
    __shared__ unsigned long long cand[2][512];
    __shared__ int cnts[2], pivots[2];
    __shared__ float cmx[3];
    __shared__ float fe[500];
    __shared__ int sel[100];
    __shared__ float msh[10];

    int b = blockIdx.x, t = threadIdx.x;
    int lane = t & 31, wid = t >> 5;

    if (t < 512) hist[t] = 0u;
    if (t == 0) { cnts[0] = 0; cnts[1] = 0; }
    if (t < 3) cmx[t] = __uint_as_float(g_cmax_u[b * 3 + t]);
    __syncthreads();

    float c0m = cmx[0], c1m = cmx[1], c2m = cmx[2];

    // validity + class-select bits; keep rv in registers
    uint32_t rvq[9];
    #pragma unroll
    for (int q = 0; q < 9; q++) {
        int p = q * 1024 + t;
        float4 c = g_clip4[(size_t)b * NPIX + p];
        uint2 bb = g_bits2[(size_t)b * NPIX + p];
        float v0 = c.x / c0m;
        float v1 = c.y / c1m;
        float v2 = c.z / c2m;
        bool fg = (v0 > 0.0f && v0 < 0.6f) || (v1 > 0.0f && v1 < 0.6f) || (v2 > 0.0f && v2 < 0.6f);
        uint32_t bits = fg ? bb.x : bb.y;
        rvq[q] = ((bits >> 9) + 1u) | (fg ? 0u : (1u << 24));
        atomicAdd(&hist[(fg ? 0 : 256) + (bits >> 24)], 1u);
    }
    __syncthreads();

    // pivots: warp 0 -> fg, warp 1 -> bg
    if (wid < 2) {
        const uint32_t* sh = hist + wid * 256;
        int csum = 0;
        #pragma unroll
        for (int i = 0; i < 8; i++) csum += (int)sh[lane * 8 + i];
        int suf = csum;
        #pragma unroll
        for (int o = 1; o < 32; o <<= 1) {
            int v = __shfl_down_sync(0xFFFFFFFFu, suf, o);
            if (lane + o < 32) suf += v;
        }
        unsigned ball = __ballot_sync(0xFFFFFFFFu, suf >= NS);
        if (ball) {
            int L = 31 - __clz(ball);
            if (lane == L) {
                int acc = suf - csum;
                int pv = 8 * L;
                for (int bin = 8 * L + 7; bin >= 8 * L; bin--) {
                    acc += (int)sh[bin];
                    if (acc >= NS) { pv = bin; break; }
                }
                pivots[wid] = pv;
            }
        } else if (lane == 0) pivots[wid] = -1;
    }
    __syncthreads();

    // collect candidates (both classes) from register-held rv
    int pv0 = pivots[0], pv1 = pivots[1];
    #pragma unroll
    for (int q = 0; q < 9; q++) {
        int p = q * 1024 + t;
        uint32_t rv = rvq[q];
        int clsv = (int)(rv >> 24);
        uint32_t v = rv & 0xFFFFFFu;
        int pvo = clsv ? pv1 : pv0;
        bool take = (pvo >= 0) ? ((int)((v - 1u) >> 15) >= pvo) : true;
        if (take) {
            int slot = atomicAdd(&cnts[clsv], 1);
            if (slot < 512)
                cand[clsv][slot] = ((unsigned long long)v << 14) |
                                   (unsigned long long)(NPIX - 1 - p);
        }
        int o = 1 - clsv;
        if (((o ? pv1 : pv0) < 0) && p < 100) {
            int slot = atomicAdd(&cnts[o], 1);
            if (slot < 512)
                cand[o][slot] = (unsigned long long)(NPIX - 1 - p);
        }
    }
    __syncthreads();

    // rank by all-pairs count (keys unique -> exact lax.top_k order)
    {
        int cls = t >> 9, i = t & 511;
        int cnt = cnts[cls] < 512 ? cnts[cls] : 512;
        if (i < cnt) {
            unsigned long long ki = cand[cls][i];
            int rank = 0;
            for (int j = 0; j < cnt; j++) rank += (cand[cls][j] > ki);
            if (rank < NS)
                sel[cls * NS + rank] = NPIX - 1 - (int)(ki & 0x3FFFull);
        }
    }
    __syncthreads();

    // train features + stats + packed negated output
    if (t < 100) {
        int p = sel[t];
        int i = p / WW, j = p % WW;
        float4 c = g_clip4[(size_t)b * NPIX + p];
        fe[t * 5 + 0] = c.x / 255.0f;
        fe[t * 5 + 1] = c.y / 255.0f;
        fe[t * 5 + 2] = c.z / 255.0f;
        fe[t * 5 + 3] = ((float)i / 96.0f) * 100.0f;
        fe[t * 5 + 4] = ((float)j / 96.0f) * 100.0f;
    }
    __syncthreads();
    if (t < 5) {
        float s = 0.0f;
        for (int r = 0; r < 100; r++) s += fe[r * 5 + t];
        float m = s / 100.0f;
        float v = 0.0f;
        for (int r = 0; r < 100; r++) { float d = fe[r * 5 + t] - m; v += d * d; }
        msh[t] = m;
        msh[5 + t] = sqrtf(v / 100.0f);
    }
    __syncthreads();
    if (t < 100) {
        int m = t >> 1, h = t & 1;
        float* dst = g_trp + ((size_t)b * 50 + m) * 12;
        #pragma unroll
        for (int f = 0; f < 5; f++)
            dst[f * 2 + h] = -((fe[t * 5 + f] - msh[f]) / msh[5 + f]);
        dst[5 * 2 + h] = 0.0f;
    }
    if (t < 10) g_ms[b * 10 + t] = msh[t];
}

// ============ K3: KNN segmentation (count trick) + masking ============
__global__ void __launch_bounds__(1024) k_seg(float* __restrict__ out) {
    __shared__ ulonglong2 stq[150];  // 50 pairs x 3 ulonglong2 = 600 floats
    __shared__ float ms[10];
    int b = blockIdx.y, t = threadIdx.x;

    if (t < 150) ((float4*)stq)[t] = ((const float4*)(g_trp + (size_t)b * 600))[t];
    if (t < 10) ms[t] = g_ms[b * 10 + t];
    __syncthreads();

    int p = blockIdx.x * 1024 + t;
    float4 c = g_clip4[(size_t)b * NPIX + p];
    int i = p / WW, j = p % WW;

    float ts0 = (c.x / 255.0f - ms[0]) / ms[5];
    float ts1 = (c.y / 255.0f - ms[1]) / ms[6];
    float ts2 = (c.z / 255.0f - ms[2]) / ms[7];
    float ts3 = (((float)i / 96.0f) * 100.0f - ms[3]) / ms[8];
    float ts4 = (((float)j / 96.0f) * 100.0f - ms[4]) / ms[9];

    uint64_t tp0 = pk2(ts0, ts0), tp1 = pk2(ts1, ts1), tp2 = pk2(ts2, ts2);
    uint64_t tp3 = pk2(ts3, ts3), tp4 = pk2(ts4, ts4);

    const float INF = __int_as_float(0x7F800000);
    float a1 = INF, a2 = INF;                       // 2 smallest fg d2

    #pragma unroll 5
    for (int m = 0; m < 25; m++) {                  // fg pairs
        ulonglong2 q0 = stq[3 * m], q1 = stq[3 * m + 1], q2 = stq[3 * m + 2];
        uint64_t d0 = add2(tp0, q0.x), d1 = add2(tp1, q0.y);
        uint64_t d2_ = add2(tp2, q1.x), d3 = add2(tp3, q1.y);
        uint64_t d4 = add2(tp4, q2.x);
        uint64_t s = mul2(d0, d0);
        s = fma2(d1, d1, s); s = fma2(d2_, d2_, s);
        s = fma2(d3, d3, s); s = fma2(d4, d4, s);
        float lo, hi; unpk2(lo, hi, s);
        float u = fmaxf(lo, a1); a2 = fminf(u, a2); a1 = fminf(lo, a1);
        u = fmaxf(hi, a1);       a2 = fminf(u, a2); a1 = fminf(hi, a1);
    }

    // threshold t: smallest float x with sqrtf(x) >= sqrtf(a2); then
    // sqrtf(d2) < sqrtf(a2)  <=>  d2 < tthr   (exact, sqrt monotone)
    float sa2 = sqrtf(a2);
    uint32_t xu = __float_as_uint(a2);
    while (xu > 0u && sqrtf(__uint_as_float(xu - 1u)) >= sa2) xu--;
    float tthr = __uint_as_float(xu);

    int cnt = 0;
    #pragma unroll 5
    for (int m = 25; m < 50; m++) {                 // bg pairs
        ulonglong2 q0 = stq[3 * m], q1 = stq[3 * m + 1], q2 = stq[3 * m + 2];
        uint64_t d0 = add2(tp0, q0.x), d1 = add2(tp1, q0.y);
        uint64_t d2_ = add2(tp2, q1.x), d3 = add2(tp3, q1.y);
        uint64_t d4 = add2(tp4, q2.x);
        uint64_t s = mul2(d0, d0);
        s = fma2(d1, d1, s); s = fma2(d2_, d2_, s);
        s = fma2(d3, d3, s); s = fma2(d4, d4, s);
        float lo, hi; unpk2(lo, hi, s);
        cnt += (lo < tthr);
        cnt += (hi < tthr);
    }

    // seg = 1 iff fewer than 4 bg sqrt-distances are strictly below sqrtf(a2)
    // (== sqrtf(a2) <= sqrtf(b4), the lax.top_k-exact condition)
    bool seg = (cnt < 4);
    float* o = out + ((size_t)b * NPIX + p) * 3;
    if (seg) { o[0] = c.x; o[1] = c.y; o[2] = c.z; }
    else     { o[0] = 0.0f; o[1] = 0.0f; o[2] = 0.0f; }
}

// ---------------- launch ----------------
extern "C" void kernel_launch(void* const* d_in, const int* in_sizes, int n_in,
                              void* d_out, int out_size) {
    const float* img = (const float*)d_in[0];
    float* out = (float*)d_out;
    k1<<<NB * 9, 1024>>>(img);
    k2<<<NB, 1024>>>();
    k_seg<<<dim3(9, NB), 1024>>>(out);
}

// round 11
// speedup vs baseline: 1.5861x; 1.0820x over previous
#include <cuda_runtime.h>
#include <stdint.h>
#include <math.h>

#define HH 96
#define WW 96
#define NPIX 9216
#define NB 32
#define NS 50

// ---------------- scratch ----------------
__device__ float    g_trp[NB * 600];          // negated standardized, pair-packed
__device__ float    g_ms[NB * 10];            // mean[5], std[5]
__device__ float4   g_clip4[NB * NPIX];       // img_p (clipped) per pixel
__device__ uint2    g_bits2[NB * NPIX];       // threefry bits for (fg, bg) keys
__device__ uint32_t g_cmax_u[NB * 3];         // idempotent across replays

// ---------------- threefry2x32 ----------------
__device__ __forceinline__ void tf2x32(uint32_t k0, uint32_t k1,
                                       uint32_t c0, uint32_t c1,
                                       uint32_t& o0, uint32_t& o1) {
    uint32_t ks2 = k0 ^ k1 ^ 0x1BD11BDAu;
    uint32_t x0 = c0 + k0, x1 = c1 + k1;
#define TF_RND(r) { x0 += x1; x1 = (x1 << (r)) | (x1 >> (32 - (r))); x1 ^= x0; }
    TF_RND(13) TF_RND(15) TF_RND(26) TF_RND(6)   x0 += k1;  x1 += ks2 + 1u;
    TF_RND(17) TF_RND(29) TF_RND(16) TF_RND(24)  x0 += ks2; x1 += k0 + 2u;
    TF_RND(13) TF_RND(15) TF_RND(26) TF_RND(6)   x0 += k0;  x1 += k1 + 3u;
    TF_RND(17) TF_RND(29) TF_RND(16) TF_RND(24)  x0 += k1;  x1 += ks2 + 4u;
    TF_RND(13) TF_RND(15) TF_RND(26) TF_RND(6)   x0 += ks2; x1 += k0 + 5u;
#undef TF_RND
    o0 = x0; o1 = x1;
}

__device__ __forceinline__ void image_keys(int b, uint32_t& f0, uint32_t& f1,
                                           uint32_t& g0, uint32_t& g1) {
    uint32_t kb0, kb1;
    tf2x32(0u, 42u, 0u, (uint32_t)b, kb0, kb1);
    tf2x32(kb0, kb1, 0u, 0u, f0, f1);
    tf2x32(kb0, kb1, 0u, 1u, g0, g1);
}

__device__ __forceinline__ uint32_t rbits(uint32_t k0, uint32_t k1, int p) {
    uint32_t o0, o1;
    tf2x32(k0, k1, 0u, (uint32_t)p, o0, o1);
    return o0 ^ o1;
}

__device__ __forceinline__ float clip255(float x) {
    return fminf(fmaxf(x / 255.0f, 0.0f), 1.0f);
}

// ---------------- packed f32x2 helpers ----------------
__device__ __forceinline__ uint64_t pk2(float lo, float hi) {
    uint64_t r; asm("mov.b64 %0, {%1, %2};" : "=l"(r) : "f"(lo), "f"(hi)); return r;
}
__device__ __forceinline__ void unpk2(float& lo, float& hi, uint64_t v) {
    asm("mov.b64 {%0, %1}, %2;" : "=f"(lo), "=f"(hi) : "l"(v));
}
__device__ __forceinline__ uint64_t add2(uint64_t a, uint64_t b) {
    uint64_t r; asm("add.rn.f32x2 %0, %1, %2;" : "=l"(r) : "l"(a), "l"(b)); return r;
}
__device__ __forceinline__ uint64_t mul2(uint64_t a, uint64_t b) {
    uint64_t r; asm("mul.rn.f32x2 %0, %1, %2;" : "=l"(r) : "l"(a), "l"(b)); return r;
}
__device__ __forceinline__ uint64_t fma2(uint64_t a, uint64_t b, uint64_t c) {
    uint64_t r; asm("fma.rn.f32x2 %0, %1, %2, %3;" : "=l"(r) : "l"(a), "l"(b), "l"(c)); return r;
}

// ============ K1 (288 blocks): clip + cmax + dual threefry ============
__global__ void __launch_bounds__(1024) k1(const float* __restrict__ img) {
    __shared__ uint32_t keys4[4];
    __shared__ uint32_t cmu[3];
    int blk = blockIdx.x, t = threadIdx.x, lane = t & 31;
    int b = blk / 9, p = (blk % 9) * 1024 + t;

    if (t == 0) {
        uint32_t f0, f1, g0, g1;
        image_keys(b, f0, f1, g0, g1);
        keys4[0] = f0; keys4[1] = f1; keys4[2] = g0; keys4[3] = g1;
    }
    if (t < 3) cmu[t] = 0u;
    __syncthreads();

    const float* px = img + ((size_t)b * NPIX + p) * 3;
    float c0 = clip255(px[0]);
    float c1 = clip255(px[1]);
    float c2 = clip255(px[2]);
    g_clip4[(size_t)b * NPIX + p] = make_float4(c0, c1, c2, 0.0f);

    uint32_t bf = rbits(keys4[0], keys4[1], p);
    uint32_t bg_ = rbits(keys4[2], keys4[3], p);
    g_bits2[(size_t)b * NPIX + p] = make_uint2(bf, bg_);

    uint32_t r0 = __reduce_max_sync(0xFFFFFFFFu, __float_as_uint(c0));
    uint32_t r1 = __reduce_max_sync(0xFFFFFFFFu, __float_as_uint(c1));
    uint32_t r2 = __reduce_max_sync(0xFFFFFFFFu, __float_as_uint(c2));
    if (lane == 0) {
        atomicMax(&cmu[0], r0); atomicMax(&cmu[1], r1); atomicMax(&cmu[2], r2);
    }
    __syncthreads();
    if (t < 3) atomicMax(&g_cmax_u[b * 3 + t], cmu[t]);   // idempotent across replays
}

// ============ K2 (32 blocks): validity + pick + rank + train ============
__global__ void __launch_bounds__(1024) k2() {
    __shared__ uint32_t hist[512];                 // [cls][256]
    __shared__ unsigned long long cand[2][512];
    __shared__ int cnts[2], pivots[2];
    __shared__ float cmx[3];
    __shared__ float fe[500];
    __shared__ int sel[100];
    __shared__ float msh[10];

    int b = blockIdx.x, t = threadIdx.x;
    int lane = t & 31, wid = t >> 5;

    if (t < 512) hist[t] = 0u;
    if (t == 0) { cnts[0] = 0; cnts[1] = 0; }
    if (t < 3) cmx[t] = __uint_as_float(g_cmax_u[b * 3 + t]);
    __syncthreads();

    float c0m = cmx[0], c1m = cmx[1], c2m = cmx[2];

    // validity + class-select bits; keep rv in registers
    uint32_t rvq[9];
    #pragma unroll
    for (int q = 0; q < 9; q++) {
        int p = q * 1024 + t;
        float4 c = g_clip4[(size_t)b * NPIX + p];
        uint2 bb = g_bits2[(size_t)b * NPIX + p];
        float v0 = c.x / c0m;
        float v1 = c.y / c1m;
        float v2 = c.z / c2m;
        bool fg = (v0 > 0.0f && v0 < 0.6f) || (v1 > 0.0f && v1 < 0.6f) || (v2 > 0.0f && v2 < 0.6f);
        uint32_t bits = fg ? bb.x : bb.y;
        rvq[q] = ((bits >> 9) + 1u) | (fg ? 0u : (1u << 24));
        atomicAdd(&hist[(fg ? 0 : 256) + (bits >> 24)], 1u);
    }
    __syncthreads();

    // pivots: warp 0 -> fg, warp 1 -> bg
    if (wid < 2) {
        const uint32_t* sh = hist + wid * 256;
        int csum = 0;
        #pragma unroll
        for (int i = 0; i < 8; i++) csum += (int)sh[lane * 8 + i];
        int suf = csum;
        #pragma unroll
        for (int o = 1; o < 32; o <<= 1) {
            int v = __shfl_down_sync(0xFFFFFFFFu, suf, o);
            if (lane + o < 32) suf += v;
        }
        unsigned ball = __ballot_sync(0xFFFFFFFFu, suf >= NS);
        if (ball) {
            int L = 31 - __clz(ball);
            if (lane == L) {
                int acc = suf - csum;
                int pv = 8 * L;
                for (int bin = 8 * L + 7; bin >= 8 * L; bin--) {
                    acc += (int)sh[bin];
                    if (acc >= NS) { pv = bin; break; }
                }
                pivots[wid] = pv;
            }
        } else if (lane == 0) pivots[wid] = -1;
    }
    __syncthreads();

    // collect candidates (both classes) from register-held rv
    int pv0 = pivots[0], pv1 = pivots[1];
    #pragma unroll
    for (int q = 0; q < 9; q++) {
        int p = q * 1024 + t;
        uint32_t rv = rvq[q];
        int clsv = (int)(rv >> 24);
        uint32_t v = rv & 0xFFFFFFu;
        int pvo = clsv ? pv1 : pv0;
        bool take = (pvo >= 0) ? ((int)((v - 1u) >> 15) >= pvo) : true;
        if (take) {
            int slot = atomicAdd(&cnts[clsv], 1);
            if (slot < 512)
                cand[clsv][slot] = ((unsigned long long)v << 14) |
                                   (unsigned long long)(NPIX - 1 - p);
        }
        int o = 1 - clsv;
        if (((o ? pv1 : pv0) < 0) && p < 100) {
            int slot = atomicAdd(&cnts[o], 1);
            if (slot < 512)
                cand[o][slot] = (unsigned long long)(NPIX - 1 - p);
        }
    }
    __syncthreads();

    // rank by all-pairs count (keys unique -> exact lax.top_k order)
    {
        int cls = t >> 9, i = t & 511;
        int cnt = cnts[cls] < 512 ? cnts[cls] : 512;
        if (i < cnt) {
            unsigned long long ki = cand[cls][i];
            int rank = 0;
            for (int j = 0; j < cnt; j++) rank += (cand[cls][j] > ki);
            if (rank < NS)
                sel[cls * NS + rank] = NPIX - 1 - (int)(ki & 0x3FFFull);
        }
    }
    __syncthreads();

    // train features + stats + packed negated output
    if (t < 100) {
        int p = sel[t];
        int i = p / WW, j = p % WW;
        float4 c = g_clip4[(size_t)b * NPIX + p];
        fe[t * 5 + 0] = c.x / 255.0f;
        fe[t * 5 + 1] = c.y / 255.0f;
        fe[t * 5 + 2] = c.z / 255.0f;
        fe[t * 5 + 3] = ((float)i / 96.0f) * 100.0f;
        fe[t * 5 + 4] = ((float)j / 96.0f) * 100.0f;
    }
    __syncthreads();
    if (t < 5) {
        float s = 0.0f;
        for (int r = 0; r < 100; r++) s += fe[r * 5 + t];
        float m = s / 100.0f;
        float v = 0.0f;
        for (int r = 0; r < 100; r++) { float d = fe[r * 5 + t] - m; v += d * d; }
        msh[t] = m;
        msh[5 + t] = sqrtf(v / 100.0f);
    }
    __syncthreads();
    if (t < 100) {
        int m = t >> 1, h = t & 1;
        float* dst = g_trp + ((size_t)b * 50 + m) * 12;
        #pragma unroll
        for (int f = 0; f < 5; f++)
            dst[f * 2 + h] = -((fe[t * 5 + f] - msh[f]) / msh[5 + f]);
        dst[5 * 2 + h] = 0.0f;
    }
    if (t < 10) g_ms[b * 10 + t] = msh[t];
}

// ============ K3: KNN segmentation, 2 pixels/thread (count trick) ============
__global__ void __launch_bounds__(512) k_seg(float* __restrict__ out) {
    __shared__ ulonglong2 stq[150];  // 50 pairs x 3 ulonglong2 = 600 floats
    __shared__ float ms[10];
    int b = blockIdx.y, t = threadIdx.x;

    if (t < 150) ((float4*)stq)[t] = ((const float4*)(g_trp + (size_t)b * 600))[t];
    if (t < 10) ms[t] = g_ms[b * 10 + t];
    __syncthreads();

    float m0 = ms[0], m1 = ms[1], m2 = ms[2], m3 = ms[3], m4 = ms[4];
    float s0 = ms[5], s1 = ms[6], s2 = ms[7], s3 = ms[8], s4 = ms[9];

    int p0 = blockIdx.x * 1024 + t;       // pixels p0 and p0+512
    float4 cA = g_clip4[(size_t)b * NPIX + p0];
    float4 cB = g_clip4[(size_t)b * NPIX + p0 + 512];

    uint64_t tpA[5], tpB[5];
    {
        int i = p0 / WW, j = p0 % WW;
        float v;
        v = (cA.x / 255.0f - m0) / s0; tpA[0] = pk2(v, v);
        v = (cA.y / 255.0f - m1) / s1; tpA[1] = pk2(v, v);
        v = (cA.z / 255.0f - m2) / s2; tpA[2] = pk2(v, v);
        v = (((float)i / 96.0f) * 100.0f - m3) / s3; tpA[3] = pk2(v, v);
        v = (((float)j / 96.0f) * 100.0f - m4) / s4; tpA[4] = pk2(v, v);
    }
    {
        int p1 = p0 + 512;
        int i = p1 / WW, j = p1 % WW;
        float v;
        v = (cB.x / 255.0f - m0) / s0; tpB[0] = pk2(v, v);
        v = (cB.y / 255.0f - m1) / s1; tpB[1] = pk2(v, v);
        v = (cB.z / 255.0f - m2) / s2; tpB[2] = pk2(v, v);
        v = (((float)i / 96.0f) * 100.0f - m3) / s3; tpB[3] = pk2(v, v);
        v = (((float)j / 96.0f) * 100.0f - m4) / s4; tpB[4] = pk2(v, v);
    }

    const float INF = __int_as_float(0x7F800000);
    float a1A = INF, a2A = INF, a1B = INF, a2B = INF;

    #pragma unroll 5
    for (int m = 0; m < 25; m++) {                  // fg pairs, both pixels
        ulonglong2 q0 = stq[3 * m], q1 = stq[3 * m + 1], q2 = stq[3 * m + 2];
        {
            uint64_t d0 = add2(tpA[0], q0.x), d1 = add2(tpA[1], q0.y);
            uint64_t d2_ = add2(tpA[2], q1.x), d3 = add2(tpA[3], q1.y);
            uint64_t d4 = add2(tpA[4], q2.x);
            uint64_t s = mul2(d0, d0);
            s = fma2(d1, d1, s); s = fma2(d2_, d2_, s);
            s = fma2(d3, d3, s); s = fma2(d4, d4, s);
            float lo, hi; unpk2(lo, hi, s);
            float u = fmaxf(lo, a1A); a2A = fminf(u, a2A); a1A = fminf(lo, a1A);
            u = fmaxf(hi, a1A);       a2A = fminf(u, a2A); a1A = fminf(hi, a1A);
        }
        {
            uint64_t d0 = add2(tpB[0], q0.x), d1 = add2(tpB[1], q0.y);
            uint64_t d2_ = add2(tpB[2], q1.x), d3 = add2(tpB[3], q1.y);
            uint64_t d4 = add2(tpB[4], q2.x);
            uint64_t s = mul2(d0, d0);
            s = fma2(d1, d1, s); s = fma2(d2_, d2_, s);
            s = fma2(d3, d3, s); s = fma2(d4, d4, s);
            float lo, hi; unpk2(lo, hi, s);
            float u = fmaxf(lo, a1B); a2B = fminf(u, a2B); a1B = fminf(lo, a1B);
            u = fmaxf(hi, a1B);       a2B = fminf(u, a2B); a1B = fminf(hi, a1B);
        }
    }

    // threshold: smallest float x with sqrtf(x) >= sqrtf(a2) (exact ulp walk)
    float saA = sqrtf(a2A), saB = sqrtf(a2B);
    uint32_t xa = __float_as_uint(a2A);
    while (xa > 0u && sqrtf(__uint_as_float(xa - 1u)) >= saA) xa--;
    float thA = __uint_as_float(xa);
    uint32_t xb = __float_as_uint(a2B);
    while (xb > 0u && sqrtf(__uint_as_float(xb - 1u)) >= saB) xb--;
    float thB = __uint_as_float(xb);

    int cntA = 0, cntB = 0;
    #pragma unroll 5
    for (int m = 25; m < 50; m++) {                 // bg pairs, both pixels
        ulonglong2 q0 = stq[3 * m], q1 = stq[3 * m + 1], q2 = stq[3 * m + 2];
        {
            uint64_t d0 = add2(tpA[0], q0.x), d1 = add2(tpA[1], q0.y);
            uint64_t d2_ = add2(tpA[2], q1.x), d3 = add2(tpA[3], q1.y);
            uint64_t d4 = add2(tpA[4], q2.x);
            uint64_t s = mul2(d0, d0);
            s = fma2(d1, d1, s); s = fma2(d2_, d2_, s);
            s = fma2(d3, d3, s); s = fma2(d4, d4, s);
            float lo, hi; unpk2(lo, hi, s);
            cntA += (lo < thA);
            cntA += (hi < thA);
        }
        {
            uint64_t d0 = add2(tpB[0], q0.x), d1 = add2(tpB[1], q0.y);
            uint64_t d2_ = add2(tpB[2], q1.x), d3 = add2(tpB[3], q1.y);
            uint64_t d4 = add2(tpB[4], q2.x);
            uint64_t s = mul2(d0, d0);
            s = fma2(d1, d1, s); s = fma2(d2_, d2_, s);
            s = fma2(d3, d3, s); s = fma2(d4, d4, s);
            float lo, hi; unpk2(lo, hi, s);
            cntB += (lo < thB);
            cntB += (hi < thB);
        }
    }

    // seg = 1 iff fewer than 4 bg sqrt-distances strictly below sqrtf(a2)
    float* oA = out + ((size_t)b * NPIX + p0) * 3;
    if (cntA < 4) { oA[0] = cA.x; oA[1] = cA.y; oA[2] = cA.z; }
    else          { oA[0] = 0.0f; oA[1] = 0.0f; oA[2] = 0.0f; }
    float* oB = out + ((size_t)b * NPIX + p0 + 512) * 3;
    if (cntB < 4) { oB[0] = cB.x; oB[1] = cB.y; oB[2] = cB.z; }
    else          { oB[0] = 0.0f; oB[1] = 0.0f; oB[2] = 0.0f; }
}

// ---------------- launch ----------------
extern "C" void kernel_launch(void* const* d_in, const int* in_sizes, int n_in,
                              void* d_out, int out_size) {
    const float* img = (const float*)d_in[0];
    float* out = (float*)d_out;
    k1<<<NB * 9, 1024>>>(img);
    k2<<<NB, 1024>>>();
    k_seg<<<dim3(9, NB), 512>>>(out);
}

// round 12
// speedup vs baseline: 1.6992x; 1.0714x over previous
#include <cuda_runtime.h>
#include <cooperative_groups.h>
#include <stdint.h>
#include <math.h>

namespace cg = cooperative_groups;

#define HH 96
#define WW 96
#define NPIX 9216
#define NB 32
#define NS 50
#define PPB 2304   // pixels per block (cluster of 4 covers one image)

// ---------------- scratch ----------------
__device__ float    g_trp[NB * 600];          // negated standardized, pair-packed
__device__ float    g_ms[NB * 10];            // mean[5], std[5]
__device__ float4   g_clip4[NB * NPIX];       // img_p (clipped) per pixel

// ---------------- threefry2x32 ----------------
__device__ __forceinline__ void tf2x32(uint32_t k0, uint32_t k1,
                                       uint32_t c0, uint32_t c1,
                                       uint32_t& o0, uint32_t& o1) {
    uint32_t ks2 = k0 ^ k1 ^ 0x1BD11BDAu;
    uint32_t x0 = c0 + k0, x1 = c1 + k1;
#define TF_RND(r) { x0 += x1; x1 = (x1 << (r)) | (x1 >> (32 - (r))); x1 ^= x0; }
    TF_RND(13) TF_RND(15) TF_RND(26) TF_RND(6)   x0 += k1;  x1 += ks2 + 1u;
    TF_RND(17) TF_RND(29) TF_RND(16) TF_RND(24)  x0 += ks2; x1 += k0 + 2u;
    TF_RND(13) TF_RND(15) TF_RND(26) TF_RND(6)   x0 += k0;  x1 += k1 + 3u;
    TF_RND(17) TF_RND(29) TF_RND(16) TF_RND(24)  x0 += k1;  x1 += ks2 + 4u;
    TF_RND(13) TF_RND(15) TF_RND(26) TF_RND(6)   x0 += ks2; x1 += k0 + 5u;
#undef TF_RND
    o0 = x0; o1 = x1;
}

__device__ __forceinline__ void image_keys(int b, uint32_t& f0, uint32_t& f1,
                                           uint32_t& g0, uint32_t& g1) {
    uint32_t kb0, kb1;
    tf2x32(0u, 42u, 0u, (uint32_t)b, kb0, kb1);
    tf2x32(kb0, kb1, 0u, 0u, f0, f1);
    tf2x32(kb0, kb1, 0u, 1u, g0, g1);
}

__device__ __forceinline__ uint32_t rbits(uint32_t k0, uint32_t k1, int p) {
    uint32_t o0, o1;
    tf2x32(k0, k1, 0u, (uint32_t)p, o0, o1);
    return o0 ^ o1;
}

__device__ __forceinline__ float clip255(float x) {
    return fminf(fmaxf(x / 255.0f, 0.0f), 1.0f);
}

// ---------------- packed f32x2 helpers ----------------
__device__ __forceinline__ uint64_t pk2(float lo, float hi) {
    uint64_t r; asm("mov.b64 %0, {%1, %2};" : "=l"(r) : "f"(lo), "f"(hi)); return r;
}
__device__ __forceinline__ void unpk2(float& lo, float& hi, uint64_t v) {
    asm("mov.b64 {%0, %1}, %2;" : "=f"(lo), "=f"(hi) : "l"(v));
}
__device__ __forceinline__ uint64_t add2(uint64_t a, uint64_t b) {
    uint64_t r; asm("add.rn.f32x2 %0, %1, %2;" : "=l"(r) : "l"(a), "l"(b)); return r;
}
__device__ __forceinline__ uint64_t mul2(uint64_t a, uint64_t b) {
    uint64_t r; asm("mul.rn.f32x2 %0, %1, %2;" : "=l"(r) : "l"(a), "l"(b)); return r;
}
__device__ __forceinline__ uint64_t fma2(uint64_t a, uint64_t b, uint64_t c) {
    uint64_t r; asm("fma.rn.f32x2 %0, %1, %2, %3;" : "=l"(r) : "l"(a), "l"(b), "l"(c)); return r;
}

// ============ K1: fused clip+cmax+validity+pick+rank+train (cluster=image) ============
__global__ void __launch_bounds__(1024) __cluster_dims__(4, 1, 1)
k_fused(const float* __restrict__ img) {
    __shared__ uint32_t lhist[512];                 // this block's [cls][256]
    __shared__ uint32_t bmax[3];                    // this block's channel max
    __shared__ uint32_t ghist[512];                 // rank0: merged hist
    __shared__ unsigned long long cand[2 * 512];    // rank0: candidates
    __shared__ int cnts[2];                         // rank0
    __shared__ int pivots[2];                       // rank0
    __shared__ int spiv[2];
    __shared__ float cmx[3];
    __shared__ uint32_t keys4[4];
    __shared__ float fe[500];
    __shared__ int sel[100];
    __shared__ float msh[10];

    cg::cluster_group cl = cg::this_cluster();
    int rank = blockIdx.x;                          // 0..3 within cluster
    int b = blockIdx.y;
    int t = threadIdx.x, lane = t & 31, wid = t >> 5;
    int base = rank * PPB;

    if (t == 0) {
        uint32_t f0, f1, g0, g1;
        image_keys(b, f0, f1, g0, g1);
        keys4[0] = f0; keys4[1] = f1; keys4[2] = g0; keys4[3] = g1;
        cnts[0] = 0; cnts[1] = 0;
    }
    if (t < 512) { lhist[t] = 0u; ghist[t] = 0u; }
    if (t < 3) bmax[t] = 0u;
    __syncthreads();

    // ---------- phase A: clip + store + block channel max ----------
    float4 cpx[3];
    float m0 = 0.0f, m1 = 0.0f, m2 = 0.0f;
    #pragma unroll
    for (int k = 0; k < 3; k++) {
        if (k == 2 && t >= 256) break;
        int p = base + k * 1024 + t;
        const float* px = img + ((size_t)b * NPIX + p) * 3;
        float c0 = clip255(px[0]);
        float c1 = clip255(px[1]);
        float c2 = clip255(px[2]);
        cpx[k] = make_float4(c0, c1, c2, 0.0f);
        g_clip4[(size_t)b * NPIX + p] = cpx[k];
        m0 = fmaxf(m0, c0); m1 = fmaxf(m1, c1); m2 = fmaxf(m2, c2);
    }
    uint32_t r0 = __reduce_max_sync(0xFFFFFFFFu, __float_as_uint(m0));
    uint32_t r1 = __reduce_max_sync(0xFFFFFFFFu, __float_as_uint(m1));
    uint32_t r2 = __reduce_max_sync(0xFFFFFFFFu, __float_as_uint(m2));
    if (lane == 0) {
        atomicMax(&bmax[0], r0); atomicMax(&bmax[1], r1); atomicMax(&bmax[2], r2);
    }
    cl.sync();   // #1: all blocks' bmax ready

    // cluster max = max over 4 ranks' bmax (DSMEM reads)
    if (t < 3) {
        uint32_t mx = 0u;
        #pragma unroll
        for (int r = 0; r < 4; r++) {
            const uint32_t* rb = cl.map_shared_rank(bmax, r);
            mx = max(mx, rb[t]);
        }
        cmx[t] = __uint_as_float(mx);
    }
    __syncthreads();

    // ---------- phase B: validity + single threefry + local hist ----------
    float c0m = cmx[0], c1m = cmx[1], c2m = cmx[2];
    uint32_t kf0 = keys4[0], kf1 = keys4[1], kg0 = keys4[2], kg1 = keys4[3];
    uint32_t rvq[3];
    #pragma unroll
    for (int k = 0; k < 3; k++) {
        if (k == 2 && t >= 256) break;
        int p = base + k * 1024 + t;
        float4 c = cpx[k];
        float v0 = c.x / c0m;
        float v1 = c.y / c1m;
        float v2 = c.z / c2m;
        bool fg = (v0 > 0.0f && v0 < 0.6f) || (v1 > 0.0f && v1 < 0.6f) || (v2 > 0.0f && v2 < 0.6f);
        uint32_t bits = rbits(fg ? kf0 : kg0, fg ? kf1 : kg1, p);
        rvq[k] = ((bits >> 9) + 1u) | (fg ? 0u : (1u << 24));
        atomicAdd(&lhist[(fg ? 0 : 256) + (bits >> 24)], 1u);
    }
    __syncthreads();
    cl.sync();   // #2: all blocks' lhist complete

    // ---------- rank0: merge hists + pivots ----------
    if (rank == 0) {
        if (t < 512) {
            uint32_t s = 0;
            #pragma unroll
            for (int r = 0; r < 4; r++)
                s += cl.map_shared_rank(lhist, r)[t];
            ghist[t] = s;
        }
        __syncthreads();
        if (wid < 2) {
            const uint32_t* sh = ghist + wid * 256;
            int csum = 0;
            #pragma unroll
            for (int i = 0; i < 8; i++) csum += (int)sh[lane * 8 + i];
            int suf = csum;
            #pragma unroll
            for (int o = 1; o < 32; o <<= 1) {
                int v = __shfl_down_sync(0xFFFFFFFFu, suf, o);
                if (lane + o < 32) suf += v;
            }
            unsigned ball = __ballot_sync(0xFFFFFFFFu, suf >= NS);
            if (ball) {
                int L = 31 - __clz(ball);
                if (lane == L) {
                    int acc = suf - csum;
                    int pv = 8 * L;
                    for (int bin = 8 * L + 7; bin >= 8 * L; bin--) {
                        acc += (int)sh[bin];
                        if (acc >= NS) { pv = bin; break; }
                    }
                    pivots[wid] = pv;
                }
            } else if (lane == 0) pivots[wid] = -1;
        }
    }
    cl.sync();   // #3: pivots ready

    if (t < 2) spiv[t] = cl.map_shared_rank(pivots, 0)[t];
    __syncthreads();

    // ---------- deposit candidates into rank0 smem ----------
    int pv0 = spiv[0], pv1 = spiv[1];
    int* r0cnts = cl.map_shared_rank(cnts, 0);
    unsigned long long* r0cand = cl.map_shared_rank(cand, 0);
    #pragma unroll
    for (int k = 0; k < 3; k++) {
        if (k == 2 && t >= 256) break;
        int p = base + k * 1024 + t;
        uint32_t rv = rvq[k];
        int clsv = (int)(rv >> 24);
        uint32_t v = rv & 0xFFFFFFu;
        int pvo = clsv ? pv1 : pv0;
        bool take = (pvo >= 0) ? ((int)((v - 1u) >> 15) >= pvo) : true;
        if (take) {
            int slot = atomicAdd(&r0cnts[clsv], 1);
            if (slot < 512)
                r0cand[clsv * 512 + slot] = ((unsigned long long)v << 14) |
                                            (unsigned long long)(NPIX - 1 - p);
        }
        int o = 1 - clsv;
        if (((o ? pv1 : pv0) < 0) && p < 100) {
            int slot = atomicAdd(&r0cnts[o], 1);
            if (slot < 512)
                r0cand[o * 512 + slot] = (unsigned long long)(NPIX - 1 - p);
        }
    }
    cl.sync();   // #4: deposits visible to rank0

    // ---------- rank0: rank + train (others exit) ----------
    if (rank == 0) {
        {
            int cls = t >> 9, i = t & 511;
            int cnt = cnts[cls] < 512 ? cnts[cls] : 512;
            if (i < cnt) {
                unsigned long long ki = cand[cls * 512 + i];
                int rr = 0;
                for (int j = 0; j < cnt; j++) rr += (cand[cls * 512 + j] > ki);
                if (rr < NS)
                    sel[cls * NS + rr] = NPIX - 1 - (int)(ki & 0x3FFFull);
            }
        }
        __syncthreads();

        if (t < 100) {
            int p = sel[t];
            int i = p / WW, j = p % WW;
            float4 c = g_clip4[(size_t)b * NPIX + p];
            fe[t * 5 + 0] = c.x / 255.0f;
            fe[t * 5 + 1] = c.y / 255.0f;
            fe[t * 5 + 2] = c.z / 255.0f;
            fe[t * 5 + 3] = ((float)i / 96.0f) * 100.0f;
            fe[t * 5 + 4] = ((float)j / 96.0f) * 100.0f;
        }
        __syncthreads();
        if (t < 5) {
            float s = 0.0f;
            for (int r = 0; r < 100; r++) s += fe[r * 5 + t];
            float m = s / 100.0f;
            float v = 0.0f;
            for (int r = 0; r < 100; r++) { float d = fe[r * 5 + t] - m; v += d * d; }
            msh[t] = m;
            msh[5 + t] = sqrtf(v / 100.0f);
        }
        __syncthreads();
        if (t < 100) {
            int m = t >> 1, h = t & 1;
            float* dst = g_trp + ((size_t)b * 50 + m) * 12;
            #pragma unroll
            for (int f = 0; f < 5; f++)
                dst[f * 2 + h] = -((fe[t * 5 + f] - msh[f]) / msh[5 + f]);
            dst[5 * 2 + h] = 0.0f;
        }
        if (t < 10) g_ms[b * 10 + t] = msh[t];
    }
}

// ============ K2: KNN segmentation, 2 pixels/thread (count trick) ============
__global__ void __launch_bounds__(512) k_seg(float* __restrict__ out) {
    __shared__ ulonglong2 stq[150];  // 50 pairs x 3 ulonglong2 = 600 floats
    __shared__ float ms[10];
    int b = blockIdx.y, t = threadIdx.x;

    if (t < 150) ((float4*)stq)[t] = ((const float4*)(g_trp + (size_t)b * 600))[t];
    if (t < 10) ms[t] = g_ms[b * 10 + t];
    __syncthreads();

    float m0 = ms[0], m1 = ms[1], m2 = ms[2], m3 = ms[3], m4 = ms[4];
    float s0 = ms[5], s1 = ms[6], s2 = ms[7], s3 = ms[8], s4 = ms[9];

    int p0 = blockIdx.x * 1024 + t;       // pixels p0 and p0+512
    float4 cA = g_clip4[(size_t)b * NPIX + p0];
    float4 cB = g_clip4[(size_t)b * NPIX + p0 + 512];

    uint64_t tpA[5], tpB[5];
    {
        int i = p0 / WW, j = p0 % WW;
        float v;
        v = (cA.x / 255.0f - m0) / s0; tpA[0] = pk2(v, v);
        v = (cA.y / 255.0f - m1) / s1; tpA[1] = pk2(v, v);
        v = (cA.z / 255.0f - m2) / s2; tpA[2] = pk2(v, v);
        v = (((float)i / 96.0f) * 100.0f - m3) / s3; tpA[3] = pk2(v, v);
        v = (((float)j / 96.0f) * 100.0f - m4) / s4; tpA[4] = pk2(v, v);
    }
    {
        int p1 = p0 + 512;
        int i = p1 / WW, j = p1 % WW;
        float v;
        v = (cB.x / 255.0f - m0) / s0; tpB[0] = pk2(v, v);
        v = (cB.y / 255.0f - m1) / s1; tpB[1] = pk2(v, v);
        v = (cB.z / 255.0f - m2) / s2; tpB[2] = pk2(v, v);
        v = (((float)i / 96.0f) * 100.0f - m3) / s3; tpB[3] = pk2(v, v);
        v = (((float)j / 96.0f) * 100.0f - m4) / s4; tpB[4] = pk2(v, v);
    }

    const float INF = __int_as_float(0x7F800000);
    float a1A = INF, a2A = INF, a1B = INF, a2B = INF;

    #pragma unroll 5
    for (int m = 0; m < 25; m++) {                  // fg pairs, both pixels
        ulonglong2 q0 = stq[3 * m], q1 = stq[3 * m + 1], q2 = stq[3 * m + 2];
        {
            uint64_t d0 = add2(tpA[0], q0.x), d1 = add2(tpA[1], q0.y);
            uint64_t d2_ = add2(tpA[2], q1.x), d3 = add2(tpA[3], q1.y);
            uint64_t d4 = add2(tpA[4], q2.x);
            uint64_t s = mul2(d0, d0);
            s = fma2(d1, d1, s); s = fma2(d2_, d2_, s);
            s = fma2(d3, d3, s); s = fma2(d4, d4, s);
            float lo, hi; unpk2(lo, hi, s);
            float u = fmaxf(lo, a1A); a2A = fminf(u, a2A); a1A = fminf(lo, a1A);
            u = fmaxf(hi, a1A);       a2A = fminf(u, a2A); a1A = fminf(hi, a1A);
        }
        {
            uint64_t d0 = add2(tpB[0], q0.x), d1 = add2(tpB[1], q0.y);
            uint64_t d2_ = add2(tpB[2], q1.x), d3 = add2(tpB[3], q1.y);
            uint64_t d4 = add2(tpB[4], q2.x);
            uint64_t s = mul2(d0, d0);
            s = fma2(d1, d1, s); s = fma2(d2_, d2_, s);
            s = fma2(d3, d3, s); s = fma2(d4, d4, s);
            float lo, hi; unpk2(lo, hi, s);
            float u = fmaxf(lo, a1B); a2B = fminf(u, a2B); a1B = fminf(lo, a1B);
            u = fmaxf(hi, a1B);       a2B = fminf(u, a2B); a1B = fminf(hi, a1B);
        }
    }

    // threshold: smallest float x with sqrtf(x) >= sqrtf(a2) (exact ulp walk)
    float saA = sqrtf(a2A), saB = sqrtf(a2B);
    uint32_t xa = __float_as_uint(a2A);
    while (xa > 0u && sqrtf(__uint_as_float(xa - 1u)) >= saA) xa--;
    float thA = __uint_as_float(xa);
    uint32_t xb = __float_as_uint(a2B);
    while (xb > 0u && sqrtf(__uint_as_float(xb - 1u)) >= saB) xb--;
    float thB = __uint_as_float(xb);

    int cntA = 0, cntB = 0;
    #pragma unroll 5
    for (int m = 25; m < 50; m++) {                 // bg pairs, both pixels
        ulonglong2 q0 = stq[3 * m], q1 = stq[3 * m + 1], q2 = stq[3 * m + 2];
        {
            uint64_t d0 = add2(tpA[0], q0.x), d1 = add2(tpA[1], q0.y);
            uint64_t d2_ = add2(tpA[2], q1.x), d3 = add2(tpA[3], q1.y);
            uint64_t d4 = add2(tpA[4], q2.x);
            uint64_t s = mul2(d0, d0);
            s = fma2(d1, d1, s); s = fma2(d2_, d2_, s);
            s = fma2(d3, d3, s); s = fma2(d4, d4, s);
            float lo, hi; unpk2(lo, hi, s);
            cntA += (lo < thA);
            cntA += (hi < thA);
        }
        {
            uint64_t d0 = add2(tpB[0], q0.x), d1 = add2(tpB[1], q0.y);
            uint64_t d2_ = add2(tpB[2], q1.x), d3 = add2(tpB[3], q1.y);
            uint64_t d4 = add2(tpB[4], q2.x);
            uint64_t s = mul2(d0, d0);
            s = fma2(d1, d1, s); s = fma2(d2_, d2_, s);
            s = fma2(d3, d3, s); s = fma2(d4, d4, s);
            float lo, hi; unpk2(lo, hi, s);
            cntB += (lo < thB);
            cntB += (hi < thB);
        }
    }

    // seg = 1 iff fewer than 4 bg sqrt-distances strictly below sqrtf(a2)
    float* oA = out + ((size_t)b * NPIX + p0) * 3;
    if (cntA < 4) { oA[0] = cA.x; oA[1] = cA.y; oA[2] = cA.z; }
    else          { oA[0] = 0.0f; oA[1] = 0.0f; oA[2] = 0.0f; }
    float* oB = out + ((size_t)b * NPIX + p0 + 512) * 3;
    if (cntB < 4) { oB[0] = cB.x; oB[1] = cB.y; oB[2] = cB.z; }
    else          { oB[0] = 0.0f; oB[1] = 0.0f; oB[2] = 0.0f; }
}

// ---------------- launch ----------------
extern "C" void kernel_launch(void* const* d_in, const int* in_sizes, int n_in,
                              void* d_out, int out_size) {
    const float* img = (const float*)d_in[0];
    float* out = (float*)d_out;
    k_fused<<<dim3(4, NB), 1024>>>(img);
    k_seg<<<dim3(9, NB), 512>>>(out);
}